// round 11
// baseline (speedup 1.0000x reference)
#include <cuda_runtime.h>

// MSD block: 12 dilated 3x3 convs (reflect pad, ReLU), channels concatenated.
// d_out holds the (4, 25, 512, 512) concat tensor; each layer reads channels
// [0, n_in) and writes [n_in, n_in+2) in place.
// Odd-D layers: R1-proven C=1 oc-packed body. Even-D layers: C=2 spatial
// f32x2 packing (aligned LDG.64 taps, zero per-tap MOVs), edge cols split
// into separate kernels so the interior instantiation has no reflect code.

#define Bdim 4
#define Hdim 512
#define Wdim 512
#define C_TOTAL 25
#define CS (Hdim * Wdim)

typedef unsigned long long u64;

__device__ __forceinline__ void fma2(u64& d, u64 a, u64 b) {
    asm("fma.rn.f32x2 %0, %1, %2, %0;" : "+l"(d) : "l"(a), "l"(b));
}
__device__ __forceinline__ u64 dup2(float v) {
    u64 r; asm("mov.b64 %0, {%1, %1};" : "=l"(r) : "f"(v)); return r;
}
__device__ __forceinline__ u64 pack2(float lo, float hi) {
    u64 r; asm("mov.b64 %0, {%1, %2};" : "=l"(r) : "f"(lo), "f"(hi)); return r;
}
__device__ __forceinline__ void unpack2(u64 v, float& lo, float& hi) {
    asm("mov.b64 {%0, %1}, %2;" : "=f"(lo), "=f"(hi) : "l"(v));
}
__device__ __forceinline__ int refl(int x) {          // reflect, H == W == 512
    return x < 0 ? -x : (x >= 512 ? 1022 - x : x);
}

// ============================ ODD-D (R1 verbatim) ===========================
template<int N_IN, int D, int R, bool REFL>
__device__ __forceinline__ void conv_body(const float* __restrict__ buf,
                                          float* __restrict__ outp,
                                          const u64* __restrict__ ws2,
                                          u64 bias2, int b, int r0, int w) {
    int wl = w - D; if (wl < 0) wl = -wl;
    int wr = w + D; if (wr >= Wdim) wr = 2 * Wdim - 2 - wr;

    u64 acc[R];
    #pragma unroll
    for (int m = 0; m < R; ++m) acc[m] = bias2;

    #pragma unroll 1
    for (int ic = 0; ic < N_IN; ++ic) {
        const float* plane = buf + ((size_t)b * C_TOTAL + ic) * CS;
        const u64* wrow = ws2 + ic * 9;
        u64 w00 = wrow[0], w01 = wrow[1], w02 = wrow[2];
        u64 w10 = wrow[3], w11 = wrow[4], w12 = wrow[5];
        u64 w20 = wrow[6], w21 = wrow[7], w22 = wrow[8];
        #pragma unroll
        for (int j = 0; j < R + 2 * D; ++j) {
            int x = r0 - D + j;
            int xr = x;
            if (REFL) {
                if (x < 0) xr = -x;
                else if (x >= Hdim) xr = 2 * Hdim - 2 - x;
            }
            const float* row = plane + (size_t)xr * Wdim;
            u64 vl = dup2(__ldg(row + wl));
            u64 vc = dup2(__ldg(row + w));
            u64 vr = dup2(__ldg(row + wr));
            if (j < R) {
                fma2(acc[j], w00, vl); fma2(acc[j], w01, vc); fma2(acc[j], w02, vr);
            }
            if (j >= D && j < R + D) {
                fma2(acc[j - D], w10, vl); fma2(acc[j - D], w11, vc); fma2(acc[j - D], w12, vr);
            }
            if (j >= 2 * D) {
                fma2(acc[j - 2 * D], w20, vl); fma2(acc[j - 2 * D], w21, vc); fma2(acc[j - 2 * D], w22, vr);
            }
        }
    }

    float* o0 = outp + ((size_t)b * C_TOTAL + N_IN) * CS + (size_t)r0 * Wdim + w;
    #pragma unroll
    for (int m = 0; m < R; ++m) {
        float lo, hi; unpack2(acc[m], lo, hi);
        o0[(size_t)m * Wdim]      = fmaxf(lo, 0.f);
        o0[CS + (size_t)m * Wdim] = fmaxf(hi, 0.f);
    }
}

template<int N_IN, int D, int R>
__global__ __launch_bounds__(128)
void conv_layer(const float* __restrict__ buf, float* __restrict__ outp,
                const float* __restrict__ wgt, const float* __restrict__ bias,
                int layer) {
    __shared__ u64 ws2[N_IN * 9];
    __shared__ u64 bsh;
    int tid = threadIdx.x;
    for (int i = tid; i < N_IN * 9; i += 128)
        ws2[i] = pack2(wgt[i], wgt[N_IN * 9 + i]);
    if (tid == 0) bsh = pack2(bias[2 * layer], bias[2 * layer + 1]);
    __syncthreads();

    int w  = blockIdx.x * 128 + tid;
    int r0 = blockIdx.y * R;
    int b  = blockIdx.z;
    u64 bias2 = bsh;

    bool interior = (r0 >= D) && (r0 + R + D <= Hdim);
    if (interior) conv_body<N_IN, D, R, false>(buf, outp, ws2, bias2, b, r0, w);
    else          conv_body<N_IN, D, R, true >(buf, outp, ws2, bias2, b, r0, w);
}

// ===================== EVEN-D: C=2 spatial f32x2 packing ====================
// Warp = R rows x 64 cols (lane owns col pair w, w+1 for BOTH out channels).
// Block = 128 thr = 4 stacked row-groups. Interior kernels: all taps are
// aligned LDG.64, zero per-tap MOVs. Edge kernels (bx 0 and 7) use reflected
// scalar loads for vl/vr, hoisted col indices.
template<int N_IN, int D, int R, bool REFLROW, bool EDGE>
__device__ __forceinline__ void conv2_body(const float* __restrict__ buf,
                                           float* __restrict__ outp,
                                           const u64* __restrict__ wsA,
                                           const u64* __restrict__ wsB,
                                           u64 bA, u64 bB, int b, int r0, int w) {
    // hoisted reflected col indices (EDGE only)
    int a0, a1, c0, c1;
    if (EDGE) {
        a0 = refl(w - D); a1 = refl(w + 1 - D);
        c0 = refl(w + D); c1 = refl(w + 1 + D);
    }

    u64 accA[R], accB[R];
    #pragma unroll
    for (int m = 0; m < R; ++m) { accA[m] = bA; accB[m] = bB; }

    #pragma unroll 1
    for (int ic = 0; ic < N_IN; ++ic) {
        const float* plane = buf + ((size_t)b * C_TOTAL + ic) * CS;
        u64 wA[9], wB[9];
        #pragma unroll
        for (int k = 0; k < 9; ++k) { wA[k] = wsA[ic * 9 + k]; wB[k] = wsB[ic * 9 + k]; }

        #pragma unroll
        for (int j = 0; j < R + 2 * D; ++j) {
            int x = r0 - D + j;
            int xr = x;
            if (REFLROW) {
                if (x < 0) xr = -x;
                else if (x >= Hdim) xr = 2 * Hdim - 2 - x;
            }
            const float* row = plane + (size_t)xr * Wdim;
            u64 vc = __ldg((const u64*)(row + w));            // w even: aligned
            u64 vl, vr;
            if (EDGE) {
                vl = pack2(__ldg(row + a0), __ldg(row + a1));
                vr = pack2(__ldg(row + c0), __ldg(row + c1));
            } else {
                vl = __ldg((const u64*)(row + (w - D)));      // D even: aligned
                vr = __ldg((const u64*)(row + (w + D)));
            }
            if (j < R) {
                fma2(accA[j], wA[0], vl); fma2(accA[j], wA[1], vc); fma2(accA[j], wA[2], vr);
                fma2(accB[j], wB[0], vl); fma2(accB[j], wB[1], vc); fma2(accB[j], wB[2], vr);
            }
            if (j >= D && j < R + D) {
                fma2(accA[j - D], wA[3], vl); fma2(accA[j - D], wA[4], vc); fma2(accA[j - D], wA[5], vr);
                fma2(accB[j - D], wB[3], vl); fma2(accB[j - D], wB[4], vc); fma2(accB[j - D], wB[5], vr);
            }
            if (j >= 2 * D) {
                fma2(accA[j - 2*D], wA[6], vl); fma2(accA[j - 2*D], wA[7], vc); fma2(accA[j - 2*D], wA[8], vr);
                fma2(accB[j - 2*D], wB[6], vl); fma2(accB[j - 2*D], wB[7], vc); fma2(accB[j - 2*D], wB[8], vr);
            }
        }
    }

    float* o = outp + ((size_t)b * C_TOTAL + N_IN) * CS + (size_t)r0 * Wdim + w;
    #pragma unroll
    for (int m = 0; m < R; ++m) {
        float lo, hi;
        unpack2(accA[m], lo, hi);
        *(float2*)(o + (size_t)m * Wdim) = make_float2(fmaxf(lo, 0.f), fmaxf(hi, 0.f));
        unpack2(accB[m], lo, hi);
        *(float2*)(o + CS + (size_t)m * Wdim) = make_float2(fmaxf(lo, 0.f), fmaxf(hi, 0.f));
    }
}

template<int N_IN, int D, int R, bool EDGE>
__global__ __launch_bounds__(128)
void conv_even(const float* __restrict__ buf, float* __restrict__ outp,
               const float* __restrict__ wgt, const float* __restrict__ bias,
               int layer) {
    __shared__ u64 wsA[N_IN * 9], wsB[N_IN * 9];
    __shared__ u64 bshA, bshB;
    int tid = threadIdx.x;
    for (int i = tid; i < N_IN * 9; i += 128) {
        wsA[i] = dup2(wgt[i]);                 // oc0 weight duplicated
        wsB[i] = dup2(wgt[9 * N_IN + i]);      // oc1 weight duplicated
    }
    if (tid == 0) { bshA = dup2(bias[2 * layer]); bshB = dup2(bias[2 * layer + 1]); }
    __syncthreads();

    const int tc = tid & 31;
    const int rg = tid >> 5;
    const int bxe = EDGE ? (blockIdx.x * 7) : (blockIdx.x + 1);  // edge: 0 or 7
    const int w  = bxe * 64 + 2 * tc;
    const int r0 = blockIdx.y * (4 * R) + rg * R;
    const int b  = blockIdx.z;
    u64 bA = bshA, bB = bshB;

    bool interior = (r0 >= D) && (r0 + R + D <= Hdim);
    if (interior) conv2_body<N_IN, D, R, false, EDGE>(buf, outp, wsA, wsB, bA, bB, b, r0, w);
    else          conv2_body<N_IN, D, R, true,  EDGE>(buf, outp, wsA, wsB, bA, bB, b, r0, w);
}

// Copy x (4,1,512,512) into channel 0 of the 25-channel output buffer.
__global__ void copy_in_kernel(const float4* __restrict__ x, float4* __restrict__ out) {
    int idx = blockIdx.x * blockDim.x + threadIdx.x;
    const int P4 = CS / 4;
    if (idx >= Bdim * P4) return;
    int b = idx / P4;
    int p = idx - b * P4;
    out[(size_t)b * (C_TOTAL * P4) + p] = x[idx];
}

extern "C" void kernel_launch(void* const* d_in, const int* in_sizes, int n_in,
                              void* d_out, int out_size) {
    const float* x    = (const float*)d_in[0];
    const float* bias = (const float*)d_in[1];
    float* out = (float*)d_out;

    {
        int total4 = Bdim * CS / 4;
        copy_in_kernel<<<(total4 + 255) / 256, 256>>>((const float4*)x, (float4*)out);
    }

    // Odd-D layers: R1 config (light R=16, heavy R=32), C=1 oc-packed.
#define ODD(i, NIN, DD, RR) \
    conv_layer<NIN, DD, RR><<<dim3(Wdim / 128, Hdim / RR, Bdim), 128>>>( \
        out, out, (const float*)d_in[2 + (i)], bias, (i))
    // Even-D layers: C=2 spatial packing; interior (bx 1..6) + edge (bx 0,7).
#define EVEN(i, NIN, DD, RR) \
    conv_even<NIN, DD, RR, false><<<dim3(6, Hdim / (4 * RR), Bdim), 128>>>( \
        out, out, (const float*)d_in[2 + (i)], bias, (i)); \
    conv_even<NIN, DD, RR, true ><<<dim3(2, Hdim / (4 * RR), Bdim), 128>>>( \
        out, out, (const float*)d_in[2 + (i)], bias, (i))

    ODD (0,  1,  1, 16);
    EVEN(1,  3,  2,  8);     // 2048 warps, matches R1 light
    ODD (2,  5,  3, 16);
    EVEN(3,  7,  4,  8);
    ODD (4,  9,  5, 32);
    EVEN(5, 11,  6, 16);     // 1024 warps, matches R1 heavy
    ODD (6, 13,  7, 32);
    EVEN(7, 15,  8, 16);
    ODD (8, 17,  9, 32);
    EVEN(9, 19, 10, 16);
    ODD (10, 21, 11, 32);
    EVEN(11, 23, 12, 16);
#undef ODD
#undef EVEN
}

// round 12
// speedup vs baseline: 1.9755x; 1.9755x over previous
#include <cuda_runtime.h>

// MSD block: 12 dilated 3x3 convs (reflect pad, ReLU), channels concatenated.
// d_out holds the (4, 25, 512, 512) concat tensor; layer i reads channels
// [0, n_in) and writes [n_in, n_in+2) in place.
// Light layers (D<=4): R1-proven body verbatim (R=16).
// Heavy layers (D>=5): same body but input channels processed in PAIRS per
// j-row (6 independent LDGs in flight before the FMA block) -> 2x per-thread
// MLP. Heavy layers are warp-supply-bound (6.9 warps/SM), so the extra
// registers are free.

#define Bdim 4
#define Hdim 512
#define Wdim 512
#define C_TOTAL 25
#define CS (Hdim * Wdim)

typedef unsigned long long u64;

__device__ __forceinline__ void fma2(u64& d, u64 a, u64 b) {
    asm("fma.rn.f32x2 %0, %1, %2, %0;" : "+l"(d) : "l"(a), "l"(b));
}
__device__ __forceinline__ u64 dup2(float v) {
    u64 r; asm("mov.b64 %0, {%1, %1};" : "=l"(r) : "f"(v)); return r;
}
__device__ __forceinline__ u64 pack2(float lo, float hi) {
    u64 r; asm("mov.b64 %0, {%1, %2};" : "=l"(r) : "f"(lo), "f"(hi)); return r;
}
__device__ __forceinline__ void unpack2(u64 v, float& lo, float& hi) {
    asm("mov.b64 {%0, %1}, %2;" : "=f"(lo), "=f"(hi) : "l"(v));
}

// ======================= LIGHT: R1 body, verbatim ==========================
template<int N_IN, int D, int R, bool REFL>
__device__ __forceinline__ void conv_body(const float* __restrict__ buf,
                                          float* __restrict__ outp,
                                          const u64* __restrict__ ws2,
                                          u64 bias2, int b, int r0, int w) {
    int wl = w - D; if (wl < 0) wl = -wl;
    int wr = w + D; if (wr >= Wdim) wr = 2 * Wdim - 2 - wr;

    u64 acc[R];
    #pragma unroll
    for (int m = 0; m < R; ++m) acc[m] = bias2;

    #pragma unroll 1
    for (int ic = 0; ic < N_IN; ++ic) {
        const float* plane = buf + ((size_t)b * C_TOTAL + ic) * CS;
        const u64* wrow = ws2 + ic * 9;
        u64 w00 = wrow[0], w01 = wrow[1], w02 = wrow[2];
        u64 w10 = wrow[3], w11 = wrow[4], w12 = wrow[5];
        u64 w20 = wrow[6], w21 = wrow[7], w22 = wrow[8];
        #pragma unroll
        for (int j = 0; j < R + 2 * D; ++j) {
            int x = r0 - D + j;
            int xr = x;
            if (REFL) {
                if (x < 0) xr = -x;
                else if (x >= Hdim) xr = 2 * Hdim - 2 - x;
            }
            const float* row = plane + (size_t)xr * Wdim;
            u64 vl = dup2(__ldg(row + wl));
            u64 vc = dup2(__ldg(row + w));
            u64 vr = dup2(__ldg(row + wr));
            if (j < R) {
                fma2(acc[j], w00, vl); fma2(acc[j], w01, vc); fma2(acc[j], w02, vr);
            }
            if (j >= D && j < R + D) {
                fma2(acc[j - D], w10, vl); fma2(acc[j - D], w11, vc); fma2(acc[j - D], w12, vr);
            }
            if (j >= 2 * D) {
                fma2(acc[j - 2 * D], w20, vl); fma2(acc[j - 2 * D], w21, vc); fma2(acc[j - 2 * D], w22, vr);
            }
        }
    }

    float* o0 = outp + ((size_t)b * C_TOTAL + N_IN) * CS + (size_t)r0 * Wdim + w;
    #pragma unroll
    for (int m = 0; m < R; ++m) {
        float lo, hi; unpack2(acc[m], lo, hi);
        o0[(size_t)m * Wdim]      = fmaxf(lo, 0.f);
        o0[CS + (size_t)m * Wdim] = fmaxf(hi, 0.f);
    }
}

template<int N_IN, int D, int R>
__global__ __launch_bounds__(128)
void conv_layer(const float* __restrict__ buf, float* __restrict__ outp,
                const float* __restrict__ wgt, const float* __restrict__ bias,
                int layer) {
    __shared__ u64 ws2[N_IN * 9];
    __shared__ u64 bsh;
    int tid = threadIdx.x;
    for (int i = tid; i < N_IN * 9; i += 128)
        ws2[i] = pack2(wgt[i], wgt[N_IN * 9 + i]);
    if (tid == 0) bsh = pack2(bias[2 * layer], bias[2 * layer + 1]);
    __syncthreads();

    int w  = blockIdx.x * 128 + tid;
    int r0 = blockIdx.y * R;
    int b  = blockIdx.z;
    u64 bias2 = bsh;

    bool interior = (r0 >= D) && (r0 + R + D <= Hdim);
    if (interior) conv_body<N_IN, D, R, false>(buf, outp, ws2, bias2, b, r0, w);
    else          conv_body<N_IN, D, R, true >(buf, outp, ws2, bias2, b, r0, w);
}

// ============== HEAVY: input channels in pairs (2x MLP/thread) =============
template<int N_IN, int D, int R, bool REFL>
__device__ __forceinline__ void conv_body_p2(const float* __restrict__ buf,
                                             float* __restrict__ outp,
                                             const u64* __restrict__ ws2,
                                             u64 bias2, int b, int r0, int w) {
    int wl = w - D; if (wl < 0) wl = -wl;
    int wr = w + D; if (wr >= Wdim) wr = 2 * Wdim - 2 - wr;

    u64 acc[R];
    #pragma unroll
    for (int m = 0; m < R; ++m) acc[m] = bias2;

    const float* base = buf + (size_t)b * C_TOTAL * CS;

    #pragma unroll 1
    for (int ic = 0; ic + 1 < N_IN; ic += 2) {
        const float* p0 = base + (size_t)ic * CS;
        const float* p1 = p0 + CS;
        const u64* w0 = ws2 + ic * 9;
        const u64* w1 = w0 + 9;
        u64 a00 = w0[0], a01 = w0[1], a02 = w0[2];
        u64 a10 = w0[3], a11 = w0[4], a12 = w0[5];
        u64 a20 = w0[6], a21 = w0[7], a22 = w0[8];
        u64 c00 = w1[0], c01 = w1[1], c02 = w1[2];
        u64 c10 = w1[3], c11 = w1[4], c12 = w1[5];
        u64 c20 = w1[6], c21 = w1[7], c22 = w1[8];
        #pragma unroll
        for (int j = 0; j < R + 2 * D; ++j) {
            int x = r0 - D + j;
            int xr = x;
            if (REFL) {
                if (x < 0) xr = -x;
                else if (x >= Hdim) xr = 2 * Hdim - 2 - x;
            }
            const size_t ro = (size_t)xr * Wdim;
            const float* row0 = p0 + ro;
            const float* row1 = p1 + ro;
            // 6 independent loads issued before any FMA consumes them
            float f0l = __ldg(row0 + wl), f0c = __ldg(row0 + w), f0r = __ldg(row0 + wr);
            float f1l = __ldg(row1 + wl), f1c = __ldg(row1 + w), f1r = __ldg(row1 + wr);
            u64 v0l = dup2(f0l), v0c = dup2(f0c), v0r = dup2(f0r);
            u64 v1l = dup2(f1l), v1c = dup2(f1c), v1r = dup2(f1r);
            if (j < R) {
                fma2(acc[j], a00, v0l); fma2(acc[j], a01, v0c); fma2(acc[j], a02, v0r);
                fma2(acc[j], c00, v1l); fma2(acc[j], c01, v1c); fma2(acc[j], c02, v1r);
            }
            if (j >= D && j < R + D) {
                fma2(acc[j - D], a10, v0l); fma2(acc[j - D], a11, v0c); fma2(acc[j - D], a12, v0r);
                fma2(acc[j - D], c10, v1l); fma2(acc[j - D], c11, v1c); fma2(acc[j - D], c12, v1r);
            }
            if (j >= 2 * D) {
                fma2(acc[j - 2*D], a20, v0l); fma2(acc[j - 2*D], a21, v0c); fma2(acc[j - 2*D], a22, v0r);
                fma2(acc[j - 2*D], c20, v1l); fma2(acc[j - 2*D], c21, v1c); fma2(acc[j - 2*D], c22, v1r);
            }
        }
    }

    // tail channel (N_IN is odd)
    {
        const int ic = N_IN - 1;
        const float* plane = base + (size_t)ic * CS;
        const u64* wrow = ws2 + ic * 9;
        u64 w00 = wrow[0], w01 = wrow[1], w02 = wrow[2];
        u64 w10 = wrow[3], w11 = wrow[4], w12 = wrow[5];
        u64 w20 = wrow[6], w21 = wrow[7], w22 = wrow[8];
        #pragma unroll
        for (int j = 0; j < R + 2 * D; ++j) {
            int x = r0 - D + j;
            int xr = x;
            if (REFL) {
                if (x < 0) xr = -x;
                else if (x >= Hdim) xr = 2 * Hdim - 2 - x;
            }
            const float* row = plane + (size_t)xr * Wdim;
            u64 vl = dup2(__ldg(row + wl));
            u64 vc = dup2(__ldg(row + w));
            u64 vr = dup2(__ldg(row + wr));
            if (j < R) {
                fma2(acc[j], w00, vl); fma2(acc[j], w01, vc); fma2(acc[j], w02, vr);
            }
            if (j >= D && j < R + D) {
                fma2(acc[j - D], w10, vl); fma2(acc[j - D], w11, vc); fma2(acc[j - D], w12, vr);
            }
            if (j >= 2 * D) {
                fma2(acc[j - 2 * D], w20, vl); fma2(acc[j - 2 * D], w21, vc); fma2(acc[j - 2 * D], w22, vr);
            }
        }
    }

    float* o0 = outp + ((size_t)b * C_TOTAL + N_IN) * CS + (size_t)r0 * Wdim + w;
    #pragma unroll
    for (int m = 0; m < R; ++m) {
        float lo, hi; unpack2(acc[m], lo, hi);
        o0[(size_t)m * Wdim]      = fmaxf(lo, 0.f);
        o0[CS + (size_t)m * Wdim] = fmaxf(hi, 0.f);
    }
}

template<int N_IN, int D, int R>
__global__ __launch_bounds__(128)
void conv_layer_p2(const float* __restrict__ buf, float* __restrict__ outp,
                   const float* __restrict__ wgt, const float* __restrict__ bias,
                   int layer) {
    __shared__ u64 ws2[N_IN * 9];
    __shared__ u64 bsh;
    int tid = threadIdx.x;
    for (int i = tid; i < N_IN * 9; i += 128)
        ws2[i] = pack2(wgt[i], wgt[N_IN * 9 + i]);
    if (tid == 0) bsh = pack2(bias[2 * layer], bias[2 * layer + 1]);
    __syncthreads();

    int w  = blockIdx.x * 128 + tid;
    int r0 = blockIdx.y * R;
    int b  = blockIdx.z;
    u64 bias2 = bsh;

    bool interior = (r0 >= D) && (r0 + R + D <= Hdim);
    if (interior) conv_body_p2<N_IN, D, R, false>(buf, outp, ws2, bias2, b, r0, w);
    else          conv_body_p2<N_IN, D, R, true >(buf, outp, ws2, bias2, b, r0, w);
}

// Copy x (4,1,512,512) into channel 0 of the 25-channel output buffer.
__global__ void copy_in_kernel(const float4* __restrict__ x, float4* __restrict__ out) {
    int idx = blockIdx.x * blockDim.x + threadIdx.x;
    const int P4 = CS / 4;
    if (idx >= Bdim * P4) return;
    int b = idx / P4;
    int p = idx - b * P4;
    out[(size_t)b * (C_TOTAL * P4) + p] = x[idx];
}

extern "C" void kernel_launch(void* const* d_in, const int* in_sizes, int n_in,
                              void* d_out, int out_size) {
    const float* x    = (const float*)d_in[0];
    const float* bias = (const float*)d_in[1];
    float* out = (float*)d_out;

    {
        int total4 = Bdim * CS / 4;
        copy_in_kernel<<<(total4 + 255) / 256, 256>>>((const float4*)x, (float4*)out);
    }

#define LIGHT(i, NIN, DD, RR) \
    conv_layer<NIN, DD, RR><<<dim3(Wdim / 128, Hdim / RR, Bdim), 128>>>( \
        out, out, (const float*)d_in[2 + (i)], bias, (i))
#define HEAVY(i, NIN, DD, RR) \
    conv_layer_p2<NIN, DD, RR><<<dim3(Wdim / 128, Hdim / RR, Bdim), 128>>>( \
        out, out, (const float*)d_in[2 + (i)], bias, (i))

    LIGHT(0,  1,  1, 16);
    LIGHT(1,  3,  2, 16);
    LIGHT(2,  5,  3, 16);
    LIGHT(3,  7,  4, 16);
    HEAVY(4,  9,  5, 32);
    HEAVY(5,  11, 6, 32);
    HEAVY(6,  13, 7, 32);
    HEAVY(7,  15, 8, 32);
    HEAVY(8,  17, 9, 32);
    HEAVY(9,  19, 10, 32);
    HEAVY(10, 21, 11, 32);
    HEAVY(11, 23, 12, 32);
#undef LIGHT
#undef HEAVY
}